// round 4
// baseline (speedup 1.0000x reference)
#include <cuda_runtime.h>
#include <cuda_bf16.h>
#include <math.h>
#include <float.h>
#include <stdint.h>

// ---------------- problem constants ----------------
#define T_TOK 8192
#define HD    2048
#define ID    1024
#define KQ    8
#define NE    128
#define KI    8192
#define I2    2048

// ---------------- fp32 scratch ----------------
__device__ float g_gate[67108864];   // [T, KI]
__device__ float g_up[67108864];     // [T, KI]
__device__ float g_sg[16777216];     // [T, I2]
__device__ float g_su[16777216];     // [T, I2]
__device__ float g_logits[1048576];  // [T, NE]
__device__ float g_wk[65536];        // [T, KQ]
__device__ float g_mix[1024];        // [NE, KQ]

// ---------------- bf16 hi/lo scratch ----------------
__device__ __nv_bfloat16 g_xh[16777216],  g_xl[16777216];   // x [T,HD]
__device__ __nv_bfloat16 g_wgh[16777216], g_wgl[16777216];  // w_gate [HD,KI]
__device__ __nv_bfloat16 g_wuh[16777216], g_wul[16777216];  // w_up
__device__ __nv_bfloat16 g_wdh[2097152],  g_wdl[2097152];   // w_down [ID,HD]
__device__ __nv_bfloat16 g_sgh[4194304],  g_sgl[4194304];   // shared_w_gate [HD,I2]
__device__ __nv_bfloat16 g_suh[4194304],  g_sul[4194304];   // shared_w_up
__device__ __nv_bfloat16 g_sdh[4194304],  g_sdl[4194304];   // shared_w_down [I2,HD]
__device__ __nv_bfloat16 g_wrh[262144],   g_wrl[262144];    // w_router [HD,NE]
__device__ __nv_bfloat16 g_zh[8388608],   g_zl[8388608];    // z [T,ID]
__device__ __nv_bfloat16 g_hh[16777216],  g_hl[16777216];   // h [T,I2]

// ================= low-level helpers =================
__device__ __forceinline__ uint32_t smem_u32(const void* p) {
    uint32_t a;
    asm("{ .reg .u64 t; cvta.to.shared.u64 t, %1; cvt.u32.u64 %0, t; }" : "=r"(a) : "l"(p));
    return a;
}
__device__ __forceinline__ void cp16(uint32_t dst, const void* src) {
    asm volatile("cp.async.cg.shared.global [%0], [%1], 16;" :: "r"(dst), "l"(src));
}
__device__ __forceinline__ void cp_commit() {
    asm volatile("cp.async.commit_group;" ::: "memory");
}
template<int N> __device__ __forceinline__ void cp_wait() {
    asm volatile("cp.async.wait_group %0;" :: "n"(N) : "memory");
}
__device__ __forceinline__ void ldsm4(uint32_t* r, uint32_t addr) {
    asm volatile("ldmatrix.sync.aligned.m8n8.x4.shared.b16 {%0,%1,%2,%3}, [%4];"
                 : "=r"(r[0]), "=r"(r[1]), "=r"(r[2]), "=r"(r[3]) : "r"(addr));
}
__device__ __forceinline__ void ldsm4t(uint32_t* r, uint32_t addr) {
    asm volatile("ldmatrix.sync.aligned.m8n8.x4.trans.shared.b16 {%0,%1,%2,%3}, [%4];"
                 : "=r"(r[0]), "=r"(r[1]), "=r"(r[2]), "=r"(r[3]) : "r"(addr));
}
__device__ __forceinline__ void mma16816(float* d, const uint32_t* a, uint32_t b0, uint32_t b1) {
    asm volatile("mma.sync.aligned.m16n8k16.row.col.f32.bf16.bf16.f32 "
                 "{%0,%1,%2,%3}, {%4,%5,%6,%7}, {%8,%9}, {%0,%1,%2,%3};"
                 : "+f"(d[0]), "+f"(d[1]), "+f"(d[2]), "+f"(d[3])
                 : "r"(a[0]), "r"(a[1]), "r"(a[2]), "r"(a[3]), "r"(b0), "r"(b1));
}

// ================= bf16x3 HMMA GEMM =================
// C[M,N] = A @ B ; A:[M,Kd] row-major hi/lo, B:[Kd,N] row-major hi/lo, C fp32.
// Block tile 128x128, Kc=64, 256 threads (8 warps of 64x32), 3-stage pipeline.
#define BM 128
#define BN 128
#define BK 64
#define A_STR 144   // (BK*2 + 16) bytes
#define B_STR 272   // (BN*2 + 16) bytes
#define SA_BYTES (BM * A_STR)          // 18432
#define SB_BYTES (BK * B_STR)          // 17408
#define STAGE_BYTES (2 * SA_BYTES + 2 * SB_BYTES)  // 71680
#define NSTAGE 3
#define GEMM_SMEM (NSTAGE * STAGE_BYTES)           // 215040

__global__ __launch_bounds__(256, 1)
void hmma3_kernel(const __nv_bfloat16* __restrict__ Ah, const __nv_bfloat16* __restrict__ Al,
                  const __nv_bfloat16* __restrict__ Bh, const __nv_bfloat16* __restrict__ Bl,
                  float* __restrict__ C, int N, int Kd, int acc)
{
    extern __shared__ char smem[];
    const uint32_t sb = smem_u32(smem);
    const int tid  = threadIdx.x;
    const int lane = tid & 31;
    const int wid  = tid >> 5;
    const int wr   = wid & 1;     // warp m-row (0..1) -> 64 rows each
    const int wc   = wid >> 1;    // warp n-col (0..3) -> 32 cols each
    const int row0 = blockIdx.x * BM;
    const int col0 = blockIdx.y * BN;
    const int nch  = Kd >> 6;

    float accf[4][4][4];
#pragma unroll
    for (int i = 0; i < 4; i++)
#pragma unroll
        for (int j = 0; j < 4; j++)
#pragma unroll
            for (int q = 0; q < 4; q++) accf[i][j][q] = 0.f;

    // precomputed per-thread load pointers/offsets
    const int a_r = tid >> 1, a_c = tid & 1;             // A: 128 rows x 8 chunks, 4 iters of (row, 2 chunks...)
    const int b_r = tid >> 4, b_c = tid & 15;            // B: 64 rows x 16 chunks

    auto load_stage = [&](int stg, int k0) {
        uint32_t s0 = sb + stg * STAGE_BYTES;
#pragma unroll
        for (int it = 0; it < 4; it++) {
            int idx = it * 256 + tid;
            int r = idx >> 3, c = idx & 7;
            const __nv_bfloat16* gh = Ah + (size_t)(row0 + r) * Kd + k0 + c * 8;
            const __nv_bfloat16* gl = Al + (size_t)(row0 + r) * Kd + k0 + c * 8;
            uint32_t d = s0 + r * A_STR + c * 16;
            cp16(d, gh);
            cp16(d + SA_BYTES, gl);
        }
#pragma unroll
        for (int it = 0; it < 4; it++) {
            int idx = it * 256 + tid;
            int r = idx >> 4, c = idx & 15;
            const __nv_bfloat16* gh = Bh + (size_t)(k0 + r) * N + col0 + c * 8;
            const __nv_bfloat16* gl = Bl + (size_t)(k0 + r) * N + col0 + c * 8;
            uint32_t d = s0 + 2 * SA_BYTES + r * B_STR + c * 16;
            cp16(d, gh);
            cp16(d + SB_BYTES, gl);
        }
        cp_commit();
    };

    // prologue: fill stages 0 and 1
    load_stage(0, 0);
    if (nch > 1) load_stage(1, 64);

    // ldmatrix lane addressing (constant parts)
    const int a_row  = wr * 64 + (lane & 15);
    const int a_colb = (lane >> 4) << 4;
    const int b_row  = lane & 15;
    const int b_colb = (wc * 32 + ((lane >> 4) << 3)) * 2;

    int stg = 0;
    for (int ch = 0; ch < nch; ch++) {
        // wait for stage ch (leave at most 1 group pending = stage ch+1)
        if (ch + 1 < nch) cp_wait<1>(); else cp_wait<0>();
        __syncthreads();
        // all warps finished compute of ch-1 -> safe to overwrite stage (ch-1)%3 == (ch+2)%3
        if (ch + 2 < nch) {
            int ns = stg + 2; if (ns >= NSTAGE) ns -= NSTAGE;
            load_stage(ns, (ch + 2) << 6);
        }

        uint32_t sA = sb + stg * STAGE_BYTES;
        uint32_t sB = sA + 2 * SA_BYTES;

#pragma unroll
        for (int ks = 0; ks < 4; ks++) {
            const int k16 = ks << 4;
            uint32_t Ahf[4][4], Alf[4][4], Bhf[2][4], Blf[2][4];
#pragma unroll
            for (int mi = 0; mi < 4; mi++) {
                uint32_t ad = sA + (a_row + mi * 16) * A_STR + k16 * 2 + a_colb;
                ldsm4(Ahf[mi], ad);
                ldsm4(Alf[mi], ad + SA_BYTES);
            }
#pragma unroll
            for (int nh = 0; nh < 2; nh++) {
                uint32_t bd = sB + (b_row + k16) * B_STR + b_colb + nh * 32;
                ldsm4t(Bhf[nh], bd);
                ldsm4t(Blf[nh], bd + SB_BYTES);
            }
#pragma unroll
            for (int mi = 0; mi < 4; mi++)
#pragma unroll
                for (int ni = 0; ni < 4; ni++) {
                    const int h = ni >> 1, q = (ni & 1) << 1;
                    mma16816(accf[mi][ni], Ahf[mi], Bhf[h][q], Bhf[h][q + 1]);
                    mma16816(accf[mi][ni], Alf[mi], Bhf[h][q], Bhf[h][q + 1]);
                    mma16816(accf[mi][ni], Ahf[mi], Blf[h][q], Blf[h][q + 1]);
                }
        }
        stg++; if (stg >= NSTAGE) stg = 0;
    }

    // epilogue
    const int er = row0 + wr * 64 + (lane >> 2);
    const int ec = col0 + wc * 32 + (lane & 3) * 2;
#pragma unroll
    for (int mi = 0; mi < 4; mi++)
#pragma unroll
        for (int ni = 0; ni < 4; ni++) {
            float* p0 = C + (size_t)(er + mi * 16) * N + ec + ni * 8;
            float* p1 = p0 + 8 * N;
            if (acc) {
                float2 o0 = *(float2*)p0, o1 = *(float2*)p1;
                accf[mi][ni][0] += o0.x; accf[mi][ni][1] += o0.y;
                accf[mi][ni][2] += o1.x; accf[mi][ni][3] += o1.y;
            }
            *(float2*)p0 = make_float2(accf[mi][ni][0], accf[mi][ni][1]);
            *(float2*)p1 = make_float2(accf[mi][ni][2], accf[mi][ni][3]);
        }
}

// ================= split fp32 -> bf16 hi/lo (float4 vectorized) =================
__global__ void split_kernel(const float4* __restrict__ src,
                             __nv_bfloat16* __restrict__ hi,
                             __nv_bfloat16* __restrict__ lo, int n4)
{
    int i = blockIdx.x * 256 + threadIdx.x;
    if (i >= n4) return;
    float4 v = src[i];
    __nv_bfloat16 h0 = __float2bfloat16_rn(v.x), h1 = __float2bfloat16_rn(v.y);
    __nv_bfloat16 h2 = __float2bfloat16_rn(v.z), h3 = __float2bfloat16_rn(v.w);
    __nv_bfloat162 hh0 = {h0, h1}, hh1 = {h2, h3};
    __nv_bfloat162 ll0 = {__float2bfloat16_rn(v.x - __bfloat162float(h0)),
                          __float2bfloat16_rn(v.y - __bfloat162float(h1))};
    __nv_bfloat162 ll1 = {__float2bfloat16_rn(v.z - __bfloat162float(h2)),
                          __float2bfloat16_rn(v.w - __bfloat162float(h3))};
    *(__nv_bfloat162*)(hi + i * 4)     = hh0;
    *(__nv_bfloat162*)(hi + i * 4 + 2) = hh1;
    *(__nv_bfloat162*)(lo + i * 4)     = ll0;
    *(__nv_bfloat162*)(lo + i * 4 + 2) = ll1;
}

// ================= amplitudes -> normalized mix =================
__global__ void mix_kernel(const float* __restrict__ amp)
{
    int e = threadIdx.x;
    if (e >= NE) return;
    float p[KQ];
    float s = 0.f;
#pragma unroll
    for (int k = 0; k < KQ; k++) {
        float a0 = amp[(e * KQ + k) * 2 + 0];
        float a1 = amp[(e * KQ + k) * 2 + 1];
        p[k] = a0 * a0 + a1 * a1;
        s += p[k];
    }
    float inv = 1.f / (s + 1e-8f);
#pragma unroll
    for (int k = 0; k < KQ; k++) g_mix[e * KQ + k] = p[k] * inv;
}

// ================= softmax + top-4 + collapse =================
__global__ void topk_kernel(const float* __restrict__ expert_scale)
{
    int lane = threadIdx.x & 31;
    int warp = threadIdx.x >> 5;
    int t = blockIdx.x * 8 + warp;
    const float* lrow = g_logits + (size_t)t * NE;

    float v[4];
#pragma unroll
    for (int j = 0; j < 4; j++) v[j] = lrow[lane + 32 * j];

    float m = fmaxf(fmaxf(v[0], v[1]), fmaxf(v[2], v[3]));
#pragma unroll
    for (int o = 16; o; o >>= 1) m = fmaxf(m, __shfl_xor_sync(0xffffffffu, m, o));

    float D = 0.f;
#pragma unroll
    for (int j = 0; j < 4; j++) D += expf(v[j] - m);
#pragma unroll
    for (int o = 16; o; o >>= 1) D += __shfl_xor_sync(0xffffffffu, D, o);

    float lv[4] = {v[0], v[1], v[2], v[3]};
    float selv[4];
    int   seli[4];
#pragma unroll
    for (int it = 0; it < 4; it++) {
        float bv = -FLT_MAX;
        int   bi = NE;
#pragma unroll
        for (int j = 0; j < 4; j++) {
            int e = lane + 32 * j;
            if (lv[j] > bv) { bv = lv[j]; bi = e; }
        }
#pragma unroll
        for (int o = 16; o; o >>= 1) {
            float ov = __shfl_xor_sync(0xffffffffu, bv, o);
            int   oi = __shfl_xor_sync(0xffffffffu, bi, o);
            if (ov > bv || (ov == bv && oi < bi)) { bv = ov; bi = oi; }
        }
        selv[it] = bv;
        seli[it] = bi;
        if ((bi & 31) == lane) lv[bi >> 5] = -FLT_MAX;
    }

    float ew[4];
    float S = 0.f;
#pragma unroll
    for (int it = 0; it < 4; it++) { ew[it] = expf(selv[it] - m); S += ew[it]; }
    float denom = S + 1e-8f * D;

    if (lane < KQ) {
        float acc = 0.f;
#pragma unroll
        for (int it = 0; it < 4; it++)
            acc += (ew[it] / denom) * expert_scale[seli[it]] * g_mix[seli[it] * KQ + lane];
        g_wk[t * KQ + lane] = acc;
    }
}

// ================= z = sum_k wk * silu(gate) * up  (writes bf16 hi/lo) =================
__global__ void moe_mix_kernel()
{
    int t = blockIdx.y;
    int i = blockIdx.x * 256 + threadIdx.x;
    __shared__ float w[KQ];
    if (threadIdx.x < KQ) w[threadIdx.x] = g_wk[t * KQ + threadIdx.x];
    __syncthreads();
    float acc = 0.f;
#pragma unroll
    for (int k = 0; k < KQ; k++) {
        size_t off = (size_t)t * KI + k * ID + i;
        float g = g_gate[off];
        float u = g_up[off];
        acc += w[k] * (g / (1.f + expf(-g))) * u;
    }
    size_t zo = (size_t)t * ID + i;
    __nv_bfloat16 h = __float2bfloat16_rn(acc);
    g_zh[zo] = h;
    g_zl[zo] = __float2bfloat16_rn(acc - __bfloat162float(h));
}

// ================= shared expert elementwise (writes bf16 hi/lo) =================
__global__ void silu_mul_kernel()
{
    size_t idx = (size_t)blockIdx.x * 256 + threadIdx.x;
    float g = g_sg[idx];
    float u = g_su[idx];
    float v = (g / (1.f + expf(-g))) * u;
    __nv_bfloat16 h = __float2bfloat16_rn(v);
    g_hh[idx] = h;
    g_hl[idx] = __float2bfloat16_rn(v - __bfloat162float(h));
}

// ================= host side =================
static void gemm3(const void* Ah, const void* Al, const void* Bh, const void* Bl,
                  float* C, int M, int N, int Kd, int acc)
{
    dim3 grid(M / BM, N / BN);
    hmma3_kernel<<<grid, 256, GEMM_SMEM>>>(
        (const __nv_bfloat16*)Ah, (const __nv_bfloat16*)Al,
        (const __nv_bfloat16*)Bh, (const __nv_bfloat16*)Bl, C, N, Kd, acc);
}

extern "C" void kernel_launch(void* const* d_in, const int* in_sizes, int n_in,
                              void* d_out, int out_size)
{
    const float* x             = (const float*)d_in[0];
    const float* w_router      = (const float*)d_in[1];
    const float* w_gate        = (const float*)d_in[2];
    const float* w_up          = (const float*)d_in[3];
    const float* w_down        = (const float*)d_in[4];
    const float* amplitudes    = (const float*)d_in[5];
    const float* expert_scale  = (const float*)d_in[6];
    const float* shared_w_gate = (const float*)d_in[7];
    const float* shared_w_up   = (const float*)d_in[8];
    const float* shared_w_down = (const float*)d_in[9];
    float* out = (float*)d_out;

    cudaFuncSetAttribute(hmma3_kernel, cudaFuncAttributeMaxDynamicSharedMemorySize, GEMM_SMEM);

    void *xh, *xl, *wgh, *wgl, *wuh, *wul, *wdh, *wdl;
    void *sgh, *sgl, *suh, *sul, *sdh, *sdl, *wrh, *wrl;
    void *zh, *zl, *hh, *hl, *pg, *pu, *psg, *psu, *plog;
    cudaGetSymbolAddress(&xh, g_xh);   cudaGetSymbolAddress(&xl, g_xl);
    cudaGetSymbolAddress(&wgh, g_wgh); cudaGetSymbolAddress(&wgl, g_wgl);
    cudaGetSymbolAddress(&wuh, g_wuh); cudaGetSymbolAddress(&wul, g_wul);
    cudaGetSymbolAddress(&wdh, g_wdh); cudaGetSymbolAddress(&wdl, g_wdl);
    cudaGetSymbolAddress(&sgh, g_sgh); cudaGetSymbolAddress(&sgl, g_sgl);
    cudaGetSymbolAddress(&suh, g_suh); cudaGetSymbolAddress(&sul, g_sul);
    cudaGetSymbolAddress(&sdh, g_sdh); cudaGetSymbolAddress(&sdl, g_sdl);
    cudaGetSymbolAddress(&wrh, g_wrh); cudaGetSymbolAddress(&wrl, g_wrl);
    cudaGetSymbolAddress(&zh, g_zh);   cudaGetSymbolAddress(&zl, g_zl);
    cudaGetSymbolAddress(&hh, g_hh);   cudaGetSymbolAddress(&hl, g_hl);
    cudaGetSymbolAddress(&pg, g_gate); cudaGetSymbolAddress(&pu, g_up);
    cudaGetSymbolAddress(&psg, g_sg);  cudaGetSymbolAddress(&psu, g_su);
    cudaGetSymbolAddress(&plog, g_logits);

    // 1. split fp32 inputs into bf16 hi/lo
    split_kernel<<<(T_TOK * HD / 4) / 256, 256>>>((const float4*)x, (__nv_bfloat16*)xh, (__nv_bfloat16*)xl, T_TOK * HD / 4);
    split_kernel<<<(HD * KI / 4) / 256, 256>>>((const float4*)w_gate, (__nv_bfloat16*)wgh, (__nv_bfloat16*)wgl, HD * KI / 4);
    split_kernel<<<(HD * KI / 4) / 256, 256>>>((const float4*)w_up, (__nv_bfloat16*)wuh, (__nv_bfloat16*)wul, HD * KI / 4);
    split_kernel<<<(ID * HD / 4) / 256, 256>>>((const float4*)w_down, (__nv_bfloat16*)wdh, (__nv_bfloat16*)wdl, ID * HD / 4);
    split_kernel<<<(HD * I2 / 4) / 256, 256>>>((const float4*)shared_w_gate, (__nv_bfloat16*)sgh, (__nv_bfloat16*)sgl, HD * I2 / 4);
    split_kernel<<<(HD * I2 / 4) / 256, 256>>>((const float4*)shared_w_up, (__nv_bfloat16*)suh, (__nv_bfloat16*)sul, HD * I2 / 4);
    split_kernel<<<(I2 * HD / 4) / 256, 256>>>((const float4*)shared_w_down, (__nv_bfloat16*)sdh, (__nv_bfloat16*)sdl, I2 * HD / 4);
    split_kernel<<<(HD * NE / 4) / 256, 256>>>((const float4*)w_router, (__nv_bfloat16*)wrh, (__nv_bfloat16*)wrl, HD * NE / 4);

    // 2. mixing weights
    mix_kernel<<<1, 128>>>(amplitudes);

    // 3. router logits [T,NE]
    gemm3(xh, xl, wrh, wrl, (float*)plog, T_TOK, NE, HD, 0);

    // 4. top-4 + collapse
    topk_kernel<<<T_TOK / 8, 256>>>(expert_scale);

    // 5. gate / up projections [T,KI]
    gemm3(xh, xl, wgh, wgl, (float*)pg, T_TOK, KI, HD, 0);
    gemm3(xh, xl, wuh, wul, (float*)pu, T_TOK, KI, HD, 0);

    // 6. z = sum_k wk * silu(gate) * up  -> bf16 hi/lo
    moe_mix_kernel<<<dim3(ID / 256, T_TOK), 256>>>();

    // 7. down projection: out = z @ w_down
    gemm3(zh, zl, wdh, wdl, out, T_TOK, HD, ID, 0);

    // 8. shared expert
    gemm3(xh, xl, sgh, sgl, (float*)psg, T_TOK, I2, HD, 0);
    gemm3(xh, xl, suh, sul, (float*)psu, T_TOK, I2, HD, 0);
    silu_mul_kernel<<<(T_TOK * I2) / 256, 256>>>();

    // 9. out += h @ shared_w_down
    gemm3(hh, hl, sdh, sdl, out, T_TOK, HD, I2, 1);
}

// round 5
// speedup vs baseline: 1.0915x; 1.0915x over previous
#include <cuda_runtime.h>
#include <cuda_bf16.h>
#include <math.h>
#include <float.h>
#include <stdint.h>

// ---------------- problem constants ----------------
#define T_TOK 8192
#define HD    2048
#define ID    1024
#define KQ    8
#define NE    128
#define KI    8192
#define I2    2048

// ---------------- fp32 scratch ----------------
__device__ float g_gate[67108864];   // [T, KI]
__device__ float g_up[67108864];     // [T, KI]
__device__ float g_sg[16777216];     // [T, I2]
__device__ float g_su[16777216];     // [T, I2]
__device__ float g_logits[1048576];  // [T, NE]
__device__ float g_wk[65536];        // [T, KQ]
__device__ float g_mix[1024];        // [NE, KQ]

// ---------------- bf16 hi/lo scratch ----------------
__device__ __nv_bfloat16 g_xh[16777216],  g_xl[16777216];   // x [T,HD]
__device__ __nv_bfloat16 g_wgh[16777216], g_wgl[16777216];  // w_gate [HD,KI]
__device__ __nv_bfloat16 g_wuh[16777216], g_wul[16777216];  // w_up
__device__ __nv_bfloat16 g_wdh[2097152],  g_wdl[2097152];   // w_down [ID,HD]
__device__ __nv_bfloat16 g_sgh[4194304],  g_sgl[4194304];   // shared_w_gate [HD,I2]
__device__ __nv_bfloat16 g_suh[4194304],  g_sul[4194304];   // shared_w_up
__device__ __nv_bfloat16 g_sdh[4194304],  g_sdl[4194304];   // shared_w_down [I2,HD]
__device__ __nv_bfloat16 g_wrh[262144],   g_wrl[262144];    // w_router [HD,NE]
__device__ __nv_bfloat16 g_zh[8388608],   g_zl[8388608];    // z [T,ID]
__device__ __nv_bfloat16 g_hh[16777216],  g_hl[16777216];   // h [T,I2]

// ================= low-level helpers =================
__device__ __forceinline__ uint32_t smem_u32(const void* p) {
    uint32_t a;
    asm("{ .reg .u64 t; cvta.to.shared.u64 t, %1; cvt.u32.u64 %0, t; }" : "=r"(a) : "l"(p));
    return a;
}
__device__ __forceinline__ void cp16(uint32_t dst, const void* src) {
    asm volatile("cp.async.cg.shared.global [%0], [%1], 16;" :: "r"(dst), "l"(src));
}
__device__ __forceinline__ void cp_commit() {
    asm volatile("cp.async.commit_group;" ::: "memory");
}
template<int N> __device__ __forceinline__ void cp_wait() {
    asm volatile("cp.async.wait_group %0;" :: "n"(N) : "memory");
}
__device__ __forceinline__ void ldsm4(uint32_t* r, uint32_t addr) {
    asm volatile("ldmatrix.sync.aligned.m8n8.x4.shared.b16 {%0,%1,%2,%3}, [%4];"
                 : "=r"(r[0]), "=r"(r[1]), "=r"(r[2]), "=r"(r[3]) : "r"(addr));
}
__device__ __forceinline__ void ldsm4t(uint32_t* r, uint32_t addr) {
    asm volatile("ldmatrix.sync.aligned.m8n8.x4.trans.shared.b16 {%0,%1,%2,%3}, [%4];"
                 : "=r"(r[0]), "=r"(r[1]), "=r"(r[2]), "=r"(r[3]) : "r"(addr));
}
__device__ __forceinline__ void mma16816(float* d, const uint32_t* a, uint32_t b0, uint32_t b1) {
    asm volatile("mma.sync.aligned.m16n8k16.row.col.f32.bf16.bf16.f32 "
                 "{%0,%1,%2,%3}, {%4,%5,%6,%7}, {%8,%9}, {%0,%1,%2,%3};"
                 : "+f"(d[0]), "+f"(d[1]), "+f"(d[2]), "+f"(d[3])
                 : "r"(a[0]), "r"(a[1]), "r"(a[2]), "r"(a[3]), "r"(b0), "r"(b1));
}

// ================= bf16x3 HMMA GEMM =================
// C[M,N] = A @ B ; A:[M,Kd] row-major hi/lo, B:[Kd,N] row-major hi/lo, C fp32.
// Block tile 128 x BN_T, Kc=64, 512 threads (16 warps, warp tile 32 x BN_T/4),
// 2-stage cp.async pipeline, single __syncthreads per chunk.
#define BM 128
#define BK 64
#define A_STR 144                      // BK*2 + 16 bytes
#define SA_HALF (BM * A_STR)           // 18432 per (hi|lo)

template<int BN_T>
__global__ __launch_bounds__(512, 1)
void hmma3_kernel(const __nv_bfloat16* __restrict__ Ah, const __nv_bfloat16* __restrict__ Al,
                  const __nv_bfloat16* __restrict__ Bh, const __nv_bfloat16* __restrict__ Bl,
                  float* __restrict__ C, int N, int Kd, int acc)
{
    constexpr int WN      = BN_T / 4;          // warp n width
    constexpr int NH      = BN_T / 64;         // n16 strips per warp
    constexpr int B_STR_T = BN_T * 2 + 16;     // bytes per B row
    constexpr int SB_HALF = BK * B_STR_T;
    constexpr int STAGEB  = 2 * SA_HALF + 2 * SB_HALF;
    constexpr int NBCH    = BN_T / 8;          // 16B chunks per B row
    constexpr int B_ITERS = (BK * NBCH) / 512;

    extern __shared__ char smem[];
    const uint32_t sb = smem_u32(smem);
    const int tid  = threadIdx.x;
    const int lane = tid & 31;
    const int wid  = tid >> 5;
    const int wr   = wid & 3;      // m strip (32 rows)
    const int wc   = wid >> 2;     // n strip (WN cols)
    const int row0 = blockIdx.x * BM;
    const int col0 = blockIdx.y * BN_T;
    const int nch  = Kd >> 6;

    float accf[2][2 * NH][4];
#pragma unroll
    for (int i = 0; i < 2; i++)
#pragma unroll
        for (int j = 0; j < 2 * NH; j++)
#pragma unroll
            for (int q = 0; q < 4; q++) accf[i][j][q] = 0.f;

    auto load_stage = [&](int stg, int k0) {
        uint32_t s0 = sb + stg * STAGEB;
#pragma unroll
        for (int it = 0; it < 2; it++) {           // A: 128 rows x 8 chunks
            int idx = it * 512 + tid;
            int r = idx >> 3, c = idx & 7;
            const __nv_bfloat16* gh = Ah + (size_t)(row0 + r) * Kd + k0 + c * 8;
            const __nv_bfloat16* gl = Al + (size_t)(row0 + r) * Kd + k0 + c * 8;
            uint32_t d = s0 + r * A_STR + c * 16;
            cp16(d, gh);
            cp16(d + SA_HALF, gl);
        }
#pragma unroll
        for (int it = 0; it < B_ITERS; it++) {     // B: 64 rows x NBCH chunks
            int idx = it * 512 + tid;
            int r = idx / NBCH, c = idx % NBCH;
            const __nv_bfloat16* gh = Bh + (size_t)(k0 + r) * N + col0 + c * 8;
            const __nv_bfloat16* gl = Bl + (size_t)(k0 + r) * N + col0 + c * 8;
            uint32_t d = s0 + 2 * SA_HALF + r * B_STR_T + c * 16;
            cp16(d, gh);
            cp16(d + SB_HALF, gl);
        }
        cp_commit();
    };

    load_stage(0, 0);

    const int a_row  = wr * 32 + (lane & 15);
    const int a_colb = (lane >> 4) << 4;
    const int b_row  = lane & 15;
    const int b_colb = (wc * WN + ((lane >> 4) << 3)) * 2;

    for (int ch = 0; ch < nch; ch++) {
        cp_wait<0>();
        __syncthreads();
        if (ch + 1 < nch) load_stage((ch + 1) & 1, (ch + 1) << 6);

        uint32_t sA = sb + (ch & 1) * STAGEB;
        uint32_t sB = sA + 2 * SA_HALF;

#pragma unroll
        for (int ks = 0; ks < 4; ks++) {
            const int k16 = ks << 4;
            uint32_t Ahf[2][4], Alf[2][4];
#pragma unroll
            for (int mi = 0; mi < 2; mi++) {
                uint32_t ad = sA + (a_row + mi * 16) * A_STR + k16 * 2 + a_colb;
                ldsm4(Ahf[mi], ad);
                ldsm4(Alf[mi], ad + SA_HALF);
            }
#pragma unroll
            for (int nh = 0; nh < NH; nh++) {
                uint32_t Bhf[4], Blf[4];
                uint32_t bd = sB + (b_row + k16) * B_STR_T + b_colb + nh * 32;
                ldsm4t(Bhf, bd);
                ldsm4t(Blf, bd + SB_HALF);
#pragma unroll
                for (int mi = 0; mi < 2; mi++)
#pragma unroll
                    for (int q = 0; q < 2; q++) {
                        float* d = accf[mi][nh * 2 + q];
                        mma16816(d, Ahf[mi], Bhf[q * 2], Bhf[q * 2 + 1]);
                        mma16816(d, Alf[mi], Bhf[q * 2], Bhf[q * 2 + 1]);
                        mma16816(d, Ahf[mi], Blf[q * 2], Blf[q * 2 + 1]);
                    }
            }
        }
    }

    // epilogue
    const int er = row0 + wr * 32 + (lane >> 2);
    const int ec = col0 + wc * WN + (lane & 3) * 2;
#pragma unroll
    for (int mi = 0; mi < 2; mi++)
#pragma unroll
        for (int ni = 0; ni < 2 * NH; ni++) {
            float* p0 = C + (size_t)(er + mi * 16) * N + ec + ni * 8;
            float* p1 = p0 + 8 * N;
            float v0 = accf[mi][ni][0], v1 = accf[mi][ni][1];
            float v2 = accf[mi][ni][2], v3 = accf[mi][ni][3];
            if (acc) {
                float2 o0 = *(float2*)p0, o1 = *(float2*)p1;
                v0 += o0.x; v1 += o0.y; v2 += o1.x; v3 += o1.y;
            }
            *(float2*)p0 = make_float2(v0, v1);
            *(float2*)p1 = make_float2(v2, v3);
        }
}

#define SMEM_256 (2 * (2 * SA_HALF + 2 * (BK * (256 * 2 + 16))))   // 208896
#define SMEM_128 (2 * (2 * SA_HALF + 2 * (BK * (128 * 2 + 16))))   // 143360

// ================= split fp32 -> bf16 hi/lo (float4 vectorized) =================
__global__ void split_kernel(const float4* __restrict__ src,
                             __nv_bfloat16* __restrict__ hi,
                             __nv_bfloat16* __restrict__ lo, int n4)
{
    int i = blockIdx.x * 256 + threadIdx.x;
    if (i >= n4) return;
    float4 v = src[i];
    __nv_bfloat16 h0 = __float2bfloat16_rn(v.x), h1 = __float2bfloat16_rn(v.y);
    __nv_bfloat16 h2 = __float2bfloat16_rn(v.z), h3 = __float2bfloat16_rn(v.w);
    __nv_bfloat162 hh0 = {h0, h1}, hh1 = {h2, h3};
    __nv_bfloat162 ll0 = {__float2bfloat16_rn(v.x - __bfloat162float(h0)),
                          __float2bfloat16_rn(v.y - __bfloat162float(h1))};
    __nv_bfloat162 ll1 = {__float2bfloat16_rn(v.z - __bfloat162float(h2)),
                          __float2bfloat16_rn(v.w - __bfloat162float(h3))};
    *(__nv_bfloat162*)(hi + i * 4)     = hh0;
    *(__nv_bfloat162*)(hi + i * 4 + 2) = hh1;
    *(__nv_bfloat162*)(lo + i * 4)     = ll0;
    *(__nv_bfloat162*)(lo + i * 4 + 2) = ll1;
}

// ================= amplitudes -> normalized mix =================
__global__ void mix_kernel(const float* __restrict__ amp)
{
    int e = threadIdx.x;
    if (e >= NE) return;
    float p[KQ];
    float s = 0.f;
#pragma unroll
    for (int k = 0; k < KQ; k++) {
        float a0 = amp[(e * KQ + k) * 2 + 0];
        float a1 = amp[(e * KQ + k) * 2 + 1];
        p[k] = a0 * a0 + a1 * a1;
        s += p[k];
    }
    float inv = 1.f / (s + 1e-8f);
#pragma unroll
    for (int k = 0; k < KQ; k++) g_mix[e * KQ + k] = p[k] * inv;
}

// ================= softmax + top-4 + collapse =================
__global__ void topk_kernel(const float* __restrict__ expert_scale)
{
    int lane = threadIdx.x & 31;
    int warp = threadIdx.x >> 5;
    int t = blockIdx.x * 8 + warp;
    const float* lrow = g_logits + (size_t)t * NE;

    float v[4];
#pragma unroll
    for (int j = 0; j < 4; j++) v[j] = lrow[lane + 32 * j];

    float m = fmaxf(fmaxf(v[0], v[1]), fmaxf(v[2], v[3]));
#pragma unroll
    for (int o = 16; o; o >>= 1) m = fmaxf(m, __shfl_xor_sync(0xffffffffu, m, o));

    float D = 0.f;
#pragma unroll
    for (int j = 0; j < 4; j++) D += expf(v[j] - m);
#pragma unroll
    for (int o = 16; o; o >>= 1) D += __shfl_xor_sync(0xffffffffu, D, o);

    float lv[4] = {v[0], v[1], v[2], v[3]};
    float selv[4];
    int   seli[4];
#pragma unroll
    for (int it = 0; it < 4; it++) {
        float bv = -FLT_MAX;
        int   bi = NE;
#pragma unroll
        for (int j = 0; j < 4; j++) {
            int e = lane + 32 * j;
            if (lv[j] > bv) { bv = lv[j]; bi = e; }
        }
#pragma unroll
        for (int o = 16; o; o >>= 1) {
            float ov = __shfl_xor_sync(0xffffffffu, bv, o);
            int   oi = __shfl_xor_sync(0xffffffffu, bi, o);
            if (ov > bv || (ov == bv && oi < bi)) { bv = ov; bi = oi; }
        }
        selv[it] = bv;
        seli[it] = bi;
        if ((bi & 31) == lane) lv[bi >> 5] = -FLT_MAX;
    }

    float ew[4];
    float S = 0.f;
#pragma unroll
    for (int it = 0; it < 4; it++) { ew[it] = expf(selv[it] - m); S += ew[it]; }
    float denom = S + 1e-8f * D;

    if (lane < KQ) {
        float acc = 0.f;
#pragma unroll
        for (int it = 0; it < 4; it++)
            acc += (ew[it] / denom) * expert_scale[seli[it]] * g_mix[seli[it] * KQ + lane];
        g_wk[t * KQ + lane] = acc;
    }
}

// ================= z = sum_k wk * silu(gate) * up  (writes bf16 hi/lo) =================
__global__ void moe_mix_kernel()
{
    int t = blockIdx.y;
    int i = blockIdx.x * 256 + threadIdx.x;
    __shared__ float w[KQ];
    if (threadIdx.x < KQ) w[threadIdx.x] = g_wk[t * KQ + threadIdx.x];
    __syncthreads();
    float acc = 0.f;
#pragma unroll
    for (int k = 0; k < KQ; k++) {
        size_t off = (size_t)t * KI + k * ID + i;
        float g = g_gate[off];
        float u = g_up[off];
        acc += w[k] * (g / (1.f + expf(-g))) * u;
    }
    size_t zo = (size_t)t * ID + i;
    __nv_bfloat16 h = __float2bfloat16_rn(acc);
    g_zh[zo] = h;
    g_zl[zo] = __float2bfloat16_rn(acc - __bfloat162float(h));
}

// ================= shared expert elementwise (writes bf16 hi/lo) =================
__global__ void silu_mul_kernel()
{
    size_t idx = (size_t)blockIdx.x * 256 + threadIdx.x;
    float g = g_sg[idx];
    float u = g_su[idx];
    float v = (g / (1.f + expf(-g))) * u;
    __nv_bfloat16 h = __float2bfloat16_rn(v);
    g_hh[idx] = h;
    g_hl[idx] = __float2bfloat16_rn(v - __bfloat162float(h));
}

// ================= host side =================
static void gemm256(const void* Ah, const void* Al, const void* Bh, const void* Bl,
                    float* C, int M, int N, int Kd, int acc)
{
    dim3 grid(M / BM, N / 256);
    hmma3_kernel<256><<<grid, 512, SMEM_256>>>(
        (const __nv_bfloat16*)Ah, (const __nv_bfloat16*)Al,
        (const __nv_bfloat16*)Bh, (const __nv_bfloat16*)Bl, C, N, Kd, acc);
}
static void gemm128(const void* Ah, const void* Al, const void* Bh, const void* Bl,
                    float* C, int M, int N, int Kd, int acc)
{
    dim3 grid(M / BM, N / 128);
    hmma3_kernel<128><<<grid, 512, SMEM_128>>>(
        (const __nv_bfloat16*)Ah, (const __nv_bfloat16*)Al,
        (const __nv_bfloat16*)Bh, (const __nv_bfloat16*)Bl, C, N, Kd, acc);
}

extern "C" void kernel_launch(void* const* d_in, const int* in_sizes, int n_in,
                              void* d_out, int out_size)
{
    const float* x             = (const float*)d_in[0];
    const float* w_router      = (const float*)d_in[1];
    const float* w_gate        = (const float*)d_in[2];
    const float* w_up          = (const float*)d_in[3];
    const float* w_down        = (const float*)d_in[4];
    const float* amplitudes    = (const float*)d_in[5];
    const float* expert_scale  = (const float*)d_in[6];
    const float* shared_w_gate = (const float*)d_in[7];
    const float* shared_w_up   = (const float*)d_in[8];
    const float* shared_w_down = (const float*)d_in[9];
    float* out = (float*)d_out;

    cudaFuncSetAttribute(hmma3_kernel<256>, cudaFuncAttributeMaxDynamicSharedMemorySize, SMEM_256);
    cudaFuncSetAttribute(hmma3_kernel<128>, cudaFuncAttributeMaxDynamicSharedMemorySize, SMEM_128);

    void *xh, *xl, *wgh, *wgl, *wuh, *wul, *wdh, *wdl;
    void *sgh, *sgl, *suh, *sul, *sdh, *sdl, *wrh, *wrl;
    void *zh, *zl, *hh, *hl, *pg, *pu, *psg, *psu, *plog;
    cudaGetSymbolAddress(&xh, g_xh);   cudaGetSymbolAddress(&xl, g_xl);
    cudaGetSymbolAddress(&wgh, g_wgh); cudaGetSymbolAddress(&wgl, g_wgl);
    cudaGetSymbolAddress(&wuh, g_wuh); cudaGetSymbolAddress(&wul, g_wul);
    cudaGetSymbolAddress(&wdh, g_wdh); cudaGetSymbolAddress(&wdl, g_wdl);
    cudaGetSymbolAddress(&sgh, g_sgh); cudaGetSymbolAddress(&sgl, g_sgl);
    cudaGetSymbolAddress(&suh, g_suh); cudaGetSymbolAddress(&sul, g_sul);
    cudaGetSymbolAddress(&sdh, g_sdh); cudaGetSymbolAddress(&sdl, g_sdl);
    cudaGetSymbolAddress(&wrh, g_wrh); cudaGetSymbolAddress(&wrl, g_wrl);
    cudaGetSymbolAddress(&zh, g_zh);   cudaGetSymbolAddress(&zl, g_zl);
    cudaGetSymbolAddress(&hh, g_hh);   cudaGetSymbolAddress(&hl, g_hl);
    cudaGetSymbolAddress(&pg, g_gate); cudaGetSymbolAddress(&pu, g_up);
    cudaGetSymbolAddress(&psg, g_sg);  cudaGetSymbolAddress(&psu, g_su);
    cudaGetSymbolAddress(&plog, g_logits);

    // 1. split fp32 inputs into bf16 hi/lo
    split_kernel<<<(T_TOK * HD / 4) / 256, 256>>>((const float4*)x, (__nv_bfloat16*)xh, (__nv_bfloat16*)xl, T_TOK * HD / 4);
    split_kernel<<<(HD * KI / 4) / 256, 256>>>((const float4*)w_gate, (__nv_bfloat16*)wgh, (__nv_bfloat16*)wgl, HD * KI / 4);
    split_kernel<<<(HD * KI / 4) / 256, 256>>>((const float4*)w_up, (__nv_bfloat16*)wuh, (__nv_bfloat16*)wul, HD * KI / 4);
    split_kernel<<<(ID * HD / 4) / 256, 256>>>((const float4*)w_down, (__nv_bfloat16*)wdh, (__nv_bfloat16*)wdl, ID * HD / 4);
    split_kernel<<<(HD * I2 / 4) / 256, 256>>>((const float4*)shared_w_gate, (__nv_bfloat16*)sgh, (__nv_bfloat16*)sgl, HD * I2 / 4);
    split_kernel<<<(HD * I2 / 4) / 256, 256>>>((const float4*)shared_w_up, (__nv_bfloat16*)suh, (__nv_bfloat16*)sul, HD * I2 / 4);
    split_kernel<<<(I2 * HD / 4) / 256, 256>>>((const float4*)shared_w_down, (__nv_bfloat16*)sdh, (__nv_bfloat16*)sdl, I2 * HD / 4);
    split_kernel<<<(HD * NE / 4) / 256, 256>>>((const float4*)w_router, (__nv_bfloat16*)wrh, (__nv_bfloat16*)wrl, HD * NE / 4);

    // 2. mixing weights
    mix_kernel<<<1, 128>>>(amplitudes);

    // 3. router logits [T,NE]
    gemm128(xh, xl, wrh, wrl, (float*)plog, T_TOK, NE, HD, 0);

    // 4. top-4 + collapse
    topk_kernel<<<T_TOK / 8, 256>>>(expert_scale);

    // 5. gate / up projections [T,KI]
    gemm256(xh, xl, wgh, wgl, (float*)pg, T_TOK, KI, HD, 0);
    gemm256(xh, xl, wuh, wul, (float*)pu, T_TOK, KI, HD, 0);

    // 6. z = sum_k wk * silu(gate) * up  -> bf16 hi/lo
    moe_mix_kernel<<<dim3(ID / 256, T_TOK), 256>>>();

    // 7. down projection: out = z @ w_down
    gemm256(zh, zl, wdh, wdl, out, T_TOK, HD, ID, 0);

    // 8. shared expert
    gemm256(xh, xl, sgh, sgl, (float*)psg, T_TOK, I2, HD, 0);
    gemm256(xh, xl, suh, sul, (float*)psu, T_TOK, I2, HD, 0);
    silu_mul_kernel<<<(T_TOK * I2) / 256, 256>>>();

    // 9. out += h @ shared_w_down
    gemm256(hh, hl, sdh, sdl, out, T_TOK, HD, I2, 1);
}